// round 8
// baseline (speedup 1.0000x reference)
#include <cuda_runtime.h>
#include <cstdint>

#define BATCHN 8
#define TT 2048
#define EE 1024
#define DD 128
#define MTOT (BATCHN*TT)

// Scratch for Q,K,V projections (8 MB each) — __device__ globals per allocation rules.
__device__ float g_q[MTOT*DD];
__device__ float g_k[MTOT*DD];
__device__ float g_v[MTOT*DD];

typedef unsigned long long ull;

__device__ __forceinline__ ull packf2(float x, float y) {
  ull r;
  asm("mov.b64 %0, {%1, %2};" : "=l"(r) : "f"(x), "f"(y));
  return r;
}
__device__ __forceinline__ void fma2(ull& c, ull a, ull b) {
  asm("fma.rn.f32x2 %0, %1, %2, %0;" : "+l"(c) : "l"(a), "l"(b));
}
union F2U { ull u; float2 f; };

__device__ __forceinline__ uint32_t smem_u32(const void* p) {
  uint32_t a;
  asm("{ .reg .u64 t; cvta.to.shared.u64 t, %1; cvt.u32.u64 %0, t; }"
      : "=r"(a) : "l"(p));
  return a;
}
__device__ __forceinline__ void cp_async16(uint32_t dst, const void* src) {
  asm volatile("cp.async.cg.shared.global [%0], [%1], 16;" :: "r"(dst),
               "l"(src) : "memory");
}
__device__ __forceinline__ void cp_commit() {
  asm volatile("cp.async.commit_group;" ::: "memory");
}
__device__ __forceinline__ void cp_wait0() {
  asm volatile("cp.async.wait_group 0;" ::: "memory");
}

// ---------------------------------------------------------------------------
// QKV projection (unchanged — measured at the scalar FFMA roofline, ~350us).
// ---------------------------------------------------------------------------
__global__ __launch_bounds__(256) void qkv_gemm_kernel(
    const float* __restrict__ X, const float* __restrict__ Wq,
    const float* __restrict__ Wk, const float* __restrict__ Wv) {
  __shared__ float Xs[8][128];
  __shared__ float Ws[8][128];
  const int which = blockIdx.y;
  const float* __restrict__ W = (which == 0) ? Wq : (which == 1) ? Wk : Wv;
  float* __restrict__ outp = (which == 0) ? g_q : (which == 1) ? g_k : g_v;

  const int m0 = blockIdx.x * 128;
  const int tid = threadIdx.x;
  const int tm = tid >> 4;
  const int tn = tid & 15;
  const int xm = tid >> 1;
  const int xk = (tid & 1) << 2;
  const int wk = tid >> 5;
  const int wn = (tid & 31) << 2;

  ull acc2[8][4];
#pragma unroll
  for (int i = 0; i < 8; i++)
#pragma unroll
    for (int j = 0; j < 4; j++) acc2[i][j] = 0ull;

  for (int k0 = 0; k0 < EE; k0 += 8) {
    float4 xv = *(const float4*)&X[(size_t)(m0 + xm) * EE + k0 + xk];
    float4 wv = *(const float4*)&W[(size_t)(k0 + wk) * DD + wn];
    __syncthreads();
    Xs[xk + 0][xm] = xv.x;
    Xs[xk + 1][xm] = xv.y;
    Xs[xk + 2][xm] = xv.z;
    Xs[xk + 3][xm] = xv.w;
    *(float4*)&Ws[wk][wn] = wv;
    __syncthreads();
#pragma unroll
    for (int kk = 0; kk < 8; kk++) {
      float a[8];
      *(float4*)&a[0] = *(const float4*)&Xs[kk][tm * 8];
      *(float4*)&a[4] = *(const float4*)&Xs[kk][tm * 8 + 4];
      ulonglong2 b01 = *(const ulonglong2*)&Ws[kk][tn * 8];
      ulonglong2 b23 = *(const ulonglong2*)&Ws[kk][tn * 8 + 4];
#pragma unroll
      for (int i = 0; i < 8; i++) {
        ull aa = packf2(a[i], a[i]);
        fma2(acc2[i][0], aa, b01.x);
        fma2(acc2[i][1], aa, b01.y);
        fma2(acc2[i][2], aa, b23.x);
        fma2(acc2[i][3], aa, b23.y);
      }
    }
  }

#pragma unroll
  for (int i = 0; i < 8; i++) {
    size_t row = (size_t)(m0 + tm * 8 + i);
    F2U u0, u1, u2, u3;
    u0.u = acc2[i][0]; u1.u = acc2[i][1];
    u2.u = acc2[i][2]; u3.u = acc2[i][3];
    float4 o0 = make_float4(u0.f.x, u0.f.y, u1.f.x, u1.f.y);
    float4 o1 = make_float4(u2.f.x, u2.f.y, u3.f.x, u3.f.y);
    *(float4*)&outp[row * DD + tn * 8] = o0;
    *(float4*)&outp[row * DD + tn * 8 + 4] = o1;
  }
}

// ---------------------------------------------------------------------------
// Causal flash attention v5: GEMM-style register blocking, BQ=64, BK=64.
// 256 threads as (ty,tx)=16x16.  S: 4 rows (ty*4+i) x 4 cols (tx+16c) per
// thread; softmax stats shfl-reduced over 16 tx lanes, kept in registers
// (same threads own same rows in PV -> alpha/l never touch smem).
// P staged via Ps[j][r] (stride 65).  PV: 4 rows x 8 d (d=tx*8) per thread.
// K/V double-buffered with cp.async; 2 barriers per tile.
// Grid (8 batch, 32 qrank), qblk=31-by -> globally heaviest-first.
// ---------------------------------------------------------------------------
#define BQ 64
#define BK 64
#define SK 132
#define PS 65
#define OFF_QS 0
#define OFF_PS 8192
#define OFF_B0 (OFF_PS + BK * PS)
#define BUF_F (BK * SK + BK * DD)
#define OFF_B1 (OFF_B0 + BUF_F)
#define ATT_SMEM ((OFF_B1 + BUF_F) * 4)

__global__ __launch_bounds__(256) void attn_kernel(float* __restrict__ out) {
  extern __shared__ float sm_[];
  float* Qs = sm_ + OFF_QS;
  float* Ps = sm_ + OFF_PS;

  const int b = blockIdx.x;
  const int qblk = 31 - (int)blockIdx.y;
  const int tid = threadIdx.x;
  const int ty = tid >> 4;
  const int tx = tid & 15;
  const float scale = 0.08838834764831845f;

  const float* __restrict__ qp = g_q + (size_t)b * TT * DD;
  const float* __restrict__ kp = g_k + (size_t)b * TT * DD;
  const float* __restrict__ vp = g_v + (size_t)b * TT * DD;

  const int lr = tid >> 5;
  const int lc4 = (tid & 31) * 4;

  {
    const size_t q0 = (size_t)qblk * BQ;
#pragma unroll
    for (int it = 0; it < 8; it++) {
      const int r = lr + 8 * it;
      float4 v = *(const float4*)&qp[(q0 + r) * DD + lc4];
      v.x *= scale; v.y *= scale; v.z *= scale; v.w *= scale;
      *(float4*)&Qs[r * DD + lc4] = v;
    }
  }

  const int nkt = qblk + 1;
  {
    const uint32_t bufa = smem_u32(sm_ + OFF_B0);
#pragma unroll
    for (int it = 0; it < 8; it++) {
      const int r = lr + 8 * it;
      cp_async16(bufa + (uint32_t)(r * SK + lc4) * 4,
                 &kp[(size_t)r * DD + lc4]);
      cp_async16(bufa + (uint32_t)(BK * SK + r * DD + lc4) * 4,
                 &vp[(size_t)r * DD + lc4]);
    }
    cp_commit();
  }

  float m = -1e30f;
  float lv[4] = {0.f, 0.f, 0.f, 0.f};
  float o[4][8];
#pragma unroll
  for (int i = 0; i < 4; i++)
#pragma unroll
    for (int j = 0; j < 8; j++) o[i][j] = 0.f;

  for (int kt = 0; kt < nkt; kt++) {
    float* buf = sm_ + ((kt & 1) ? OFF_B1 : OFF_B0);
    cp_wait0();
    __syncthreads();

    if (kt + 1 < nkt) {
      const uint32_t bufa = smem_u32(sm_ + ((kt & 1) ? OFF_B0 : OFF_B1));
      const size_t krow = (size_t)(kt + 1) * BK;
#pragma unroll
      for (int it = 0; it < 8; it++) {
        const int r = lr + 8 * it;
        cp_async16(bufa + (uint32_t)(r * SK + lc4) * 4,
                   &kp[(krow + r) * DD + lc4]);
        cp_async16(bufa + (uint32_t)(BK * SK + r * DD + lc4) * 4,
                   &vp[(krow + r) * DD + lc4]);
      }
      cp_commit();
    }

    const float* Kb = buf;
    const float* Vb = buf + BK * SK;

    // ---- S = Q K^T ----
    float s[4][4];
#pragma unroll
    for (int i = 0; i < 4; i++)
#pragma unroll
      for (int c = 0; c < 4; c++) s[i][c] = 0.f;

#pragma unroll 4
    for (int d4 = 0; d4 < DD; d4 += 4) {
      float4 qv[4], kv[4];
#pragma unroll
      for (int i = 0; i < 4; i++)
        qv[i] = *(const float4*)&Qs[(ty * 4 + i) * DD + d4];
#pragma unroll
      for (int c = 0; c < 4; c++)
        kv[c] = *(const float4*)&Kb[(tx + 16 * c) * SK + d4];
#pragma unroll
      for (int i = 0; i < 4; i++)
#pragma unroll
        for (int c = 0; c < 4; c++)
          s[i][c] += qv[i].x * kv[c].x + qv[i].y * kv[c].y +
                     qv[i].z * kv[c].z + qv[i].w * kv[c].w;
    }

    if (kt == qblk) {
#pragma unroll
      for (int i = 0; i < 4; i++) {
        const int qg = qblk * BQ + ty * 4 + i;
#pragma unroll
        for (int c = 0; c < 4; c++)
          if (kt * BK + tx + 16 * c > qg) s[i][c] = -1e30f;
      }
    }

    // ---- softmax: one running max shared by the thread's 4 rows
    // (valid: per-row shift just has to be consistent between P and l) ----
    float vmax = s[0][0];
#pragma unroll
    for (int i = 0; i < 4; i++)
#pragma unroll
      for (int c = 0; c < 4; c++) vmax = fmaxf(vmax, s[i][c]);
#pragma unroll
    for (int off = 1; off < 16; off <<= 1)
      vmax = fmaxf(vmax, __shfl_xor_sync(0xffffffffu, vmax, off));
    const float mn = fmaxf(m, vmax);
    const float al = __expf(m - mn);
    m = mn;

#pragma unroll
    for (int i = 0; i < 4; i++) {
      float p0 = __expf(s[i][0] - mn);
      float p1 = __expf(s[i][1] - mn);
      float p2 = __expf(s[i][2] - mn);
      float p3 = __expf(s[i][3] - mn);
      s[i][0] = p0; s[i][1] = p1; s[i][2] = p2; s[i][3] = p3;
      float ps = (p0 + p1) + (p2 + p3);
#pragma unroll
      for (int off = 1; off < 16; off <<= 1)
        ps += __shfl_xor_sync(0xffffffffu, ps, off);
      lv[i] = lv[i] * al + ps;
    }

#pragma unroll
    for (int c = 0; c < 4; c++)
#pragma unroll
      for (int i = 0; i < 4; i++)
        Ps[(tx + 16 * c) * PS + ty * 4 + i] = s[i][c];
    __syncthreads();

    // ---- rescale O, then O += P V ----
#pragma unroll
    for (int i = 0; i < 4; i++)
#pragma unroll
      for (int j = 0; j < 8; j++) o[i][j] *= al;

#pragma unroll 4
    for (int j = 0; j < BK; j++) {
      float p0 = Ps[j * PS + ty * 4 + 0];
      float p1 = Ps[j * PS + ty * 4 + 1];
      float p2 = Ps[j * PS + ty * 4 + 2];
      float p3 = Ps[j * PS + ty * 4 + 3];
      float4 v0 = *(const float4*)&Vb[j * DD + tx * 8];
      float4 v1 = *(const float4*)&Vb[j * DD + tx * 8 + 4];
      o[0][0] += p0 * v0.x; o[0][1] += p0 * v0.y;
      o[0][2] += p0 * v0.z; o[0][3] += p0 * v0.w;
      o[0][4] += p0 * v1.x; o[0][5] += p0 * v1.y;
      o[0][6] += p0 * v1.z; o[0][7] += p0 * v1.w;
      o[1][0] += p1 * v0.x; o[1][1] += p1 * v0.y;
      o[1][2] += p1 * v0.z; o[1][3] += p1 * v0.w;
      o[1][4] += p1 * v1.x; o[1][5] += p1 * v1.y;
      o[1][6] += p1 * v1.z; o[1][7] += p1 * v1.w;
      o[2][0] += p2 * v0.x; o[2][1] += p2 * v0.y;
      o[2][2] += p2 * v0.z; o[2][3] += p2 * v0.w;
      o[2][4] += p2 * v1.x; o[2][5] += p2 * v1.y;
      o[2][6] += p2 * v1.z; o[2][7] += p2 * v1.w;
      o[3][0] += p3 * v0.x; o[3][1] += p3 * v0.y;
      o[3][2] += p3 * v0.z; o[3][3] += p3 * v0.w;
      o[3][4] += p3 * v1.x; o[3][5] += p3 * v1.y;
      o[3][6] += p3 * v1.z; o[3][7] += p3 * v1.w;
    }
  }

#pragma unroll
  for (int i = 0; i < 4; i++) {
    const float inv = 1.f / lv[i];
    const size_t row = (size_t)b * TT + (size_t)qblk * BQ + ty * 4 + i;
    float4 a = make_float4(o[i][0] * inv, o[i][1] * inv, o[i][2] * inv,
                           o[i][3] * inv);
    float4 c = make_float4(o[i][4] * inv, o[i][5] * inv, o[i][6] * inv,
                           o[i][7] * inv);
    *(float4*)&out[row * DD + tx * 8] = a;
    *(float4*)&out[row * DD + tx * 8 + 4] = c;
  }
}

// ---------------------------------------------------------------------------
extern "C" void kernel_launch(void* const* d_in, const int* in_sizes, int n_in,
                              void* d_out, int out_size) {
  const float* X = (const float*)d_in[0];
  const float* Wq = (const float*)d_in[1];
  const float* Wk = (const float*)d_in[2];
  const float* Wv = (const float*)d_in[3];
  float* out = (float*)d_out;

  qkv_gemm_kernel<<<dim3(128, 3), 256>>>(X, Wq, Wk, Wv);

  cudaFuncSetAttribute((const void*)attn_kernel,
                       cudaFuncAttributeMaxDynamicSharedMemorySize, ATT_SMEM);
  attn_kernel<<<dim3(BATCHN, 32), 256, ATT_SMEM>>>(out);
}

// round 9
// speedup vs baseline: 1.5608x; 1.5608x over previous
#include <cuda_runtime.h>
#include <cstdint>

#define BATCHN 8
#define TT 2048
#define EE 1024
#define DD 128
#define MTOT (BATCHN*TT)

// Scratch for Q,K,V projections (8 MB each) — __device__ globals per allocation rules.
__device__ float g_q[MTOT*DD];
__device__ float g_k[MTOT*DD];
__device__ float g_v[MTOT*DD];

typedef unsigned long long ull;

__device__ __forceinline__ ull packf2(float x, float y) {
  ull r;
  asm("mov.b64 %0, {%1, %2};" : "=l"(r) : "f"(x), "f"(y));
  return r;
}
__device__ __forceinline__ void fma2(ull& c, ull a, ull b) {
  asm("fma.rn.f32x2 %0, %1, %2, %0;" : "+l"(c) : "l"(a), "l"(b));
}
union F2U { ull u; float2 f; };

// ---------------------------------------------------------------------------
// QKV projection (unchanged — measured at the scalar FFMA roofline, ~350us).
// ---------------------------------------------------------------------------
__global__ __launch_bounds__(256) void qkv_gemm_kernel(
    const float* __restrict__ X, const float* __restrict__ Wq,
    const float* __restrict__ Wk, const float* __restrict__ Wv) {
  __shared__ float Xs[8][128];
  __shared__ float Ws[8][128];
  const int which = blockIdx.y;
  const float* __restrict__ W = (which == 0) ? Wq : (which == 1) ? Wk : Wv;
  float* __restrict__ outp = (which == 0) ? g_q : (which == 1) ? g_k : g_v;

  const int m0 = blockIdx.x * 128;
  const int tid = threadIdx.x;
  const int tm = tid >> 4;
  const int tn = tid & 15;
  const int xm = tid >> 1;
  const int xk = (tid & 1) << 2;
  const int wk = tid >> 5;
  const int wn = (tid & 31) << 2;

  ull acc2[8][4];
#pragma unroll
  for (int i = 0; i < 8; i++)
#pragma unroll
    for (int j = 0; j < 4; j++) acc2[i][j] = 0ull;

  for (int k0 = 0; k0 < EE; k0 += 8) {
    float4 xv = *(const float4*)&X[(size_t)(m0 + xm) * EE + k0 + xk];
    float4 wv = *(const float4*)&W[(size_t)(k0 + wk) * DD + wn];
    __syncthreads();
    Xs[xk + 0][xm] = xv.x;
    Xs[xk + 1][xm] = xv.y;
    Xs[xk + 2][xm] = xv.z;
    Xs[xk + 3][xm] = xv.w;
    *(float4*)&Ws[wk][wn] = wv;
    __syncthreads();
#pragma unroll
    for (int kk = 0; kk < 8; kk++) {
      float a[8];
      *(float4*)&a[0] = *(const float4*)&Xs[kk][tm * 8];
      *(float4*)&a[4] = *(const float4*)&Xs[kk][tm * 8 + 4];
      ulonglong2 b01 = *(const ulonglong2*)&Ws[kk][tn * 8];
      ulonglong2 b23 = *(const ulonglong2*)&Ws[kk][tn * 8 + 4];
#pragma unroll
      for (int i = 0; i < 8; i++) {
        ull aa = packf2(a[i], a[i]);
        fma2(acc2[i][0], aa, b01.x);
        fma2(acc2[i][1], aa, b01.y);
        fma2(acc2[i][2], aa, b23.x);
        fma2(acc2[i][3], aa, b23.y);
      }
    }
  }

#pragma unroll
  for (int i = 0; i < 8; i++) {
    size_t row = (size_t)(m0 + tm * 8 + i);
    F2U u0, u1, u2, u3;
    u0.u = acc2[i][0]; u1.u = acc2[i][1];
    u2.u = acc2[i][2]; u3.u = acc2[i][3];
    float4 o0 = make_float4(u0.f.x, u0.f.y, u1.f.x, u1.f.y);
    float4 o1 = make_float4(u2.f.x, u2.f.y, u3.f.x, u3.f.y);
    *(float4*)&outp[row * DD + tn * 8] = o0;
    *(float4*)&outp[row * DD + tn * 8 + 4] = o1;
  }
}

// ---------------------------------------------------------------------------
// Causal flash attention v6: R8 compute structure + R4 scheduling.
// BQ=64, BK=64; 256 threads (ty,tx)=16x16; S tile 4x4, PV tile 4x8;
// register softmax (per-thread shared running max — per-row shift consistent).
// Single K/V smem buffer, software-pipelined register prefetch (next K loads
// during S, next V during PV), 3 barriers/tile, no cp.async.
// Grid (16, 8): CTA bx does qblk {bx, 31-bx} -> uniform 33 tiles, one wave.
// ---------------------------------------------------------------------------
#define BQ 64
#define BK 64
#define SK 132
#define PS 65
#define OFF_QS 0                        // [64][128]
#define OFF_PS (BQ * DD)                // 8192: [64][65]
#define OFF_KS (OFF_PS + BK * PS)       // 12352: [64][132]
#define OFF_VS (OFF_KS + BK * SK)       // 20800: [64][128]
#define ATT_SMEM ((OFF_VS + BK * DD) * 4)  // 115968 bytes

__global__ __launch_bounds__(256) void attn_kernel(float* __restrict__ out) {
  extern __shared__ float sm_[];
  float* Qs = sm_ + OFF_QS;
  float* Ps = sm_ + OFF_PS;
  float* Ks = sm_ + OFF_KS;
  float* Vs = sm_ + OFF_VS;

  const int b = blockIdx.y;
  const int tid = threadIdx.x;
  const int ty = tid >> 4;
  const int tx = tid & 15;
  const float scale = 0.08838834764831845f;

  const float* __restrict__ qp = g_q + (size_t)b * TT * DD;
  const float* __restrict__ kp = g_k + (size_t)b * TT * DD;
  const float* __restrict__ vp = g_v + (size_t)b * TT * DD;

  const int lr = tid >> 5;
  const int lc4 = (tid & 31) * 4;

  for (int pass = 0; pass < 2; pass++) {
    const int qblk = pass ? (31 - (int)blockIdx.x) : (int)blockIdx.x;
    __syncthreads();  // previous pass fully done before Qs overwrite

    {
      const size_t q0 = (size_t)qblk * BQ;
#pragma unroll
      for (int it = 0; it < 8; it++) {
        const int r = lr + 8 * it;
        float4 v = *(const float4*)&qp[(q0 + r) * DD + lc4];
        v.x *= scale; v.y *= scale; v.z *= scale; v.w *= scale;
        *(float4*)&Qs[r * DD + lc4] = v;
      }
    }

    const int nkt = qblk + 1;

    float m = -1e30f;
    float lv[4] = {0.f, 0.f, 0.f, 0.f};
    float o[4][8];
#pragma unroll
    for (int i = 0; i < 4; i++)
#pragma unroll
      for (int j = 0; j < 8; j++) o[i][j] = 0.f;

    float4 pk[8], pv[8];
#pragma unroll
    for (int it = 0; it < 8; it++) {
      const int r = lr + 8 * it;
      pk[it] = *(const float4*)&kp[(size_t)r * DD + lc4];
      pv[it] = *(const float4*)&vp[(size_t)r * DD + lc4];
    }

    for (int kt = 0; kt < nkt; kt++) {
      __syncthreads();  // PV(kt-1) readers done; Q staged (first iter)
#pragma unroll
      for (int it = 0; it < 8; it++) {
        const int r = lr + 8 * it;
        *(float4*)&Ks[r * SK + lc4] = pk[it];
        *(float4*)&Vs[r * DD + lc4] = pv[it];
      }
      __syncthreads();  // tiles visible

      if (kt + 1 < nkt) {
        const size_t krow = (size_t)(kt + 1) * BK;
#pragma unroll
        for (int it = 0; it < 8; it++)
          pk[it] = *(const float4*)&kp[(krow + lr + 8 * it) * DD + lc4];
      }

      // ---- S = Q K^T : 4 rows (ty*4+i) x 4 cols (tx+16c) ----
      float s[4][4];
#pragma unroll
      for (int i = 0; i < 4; i++)
#pragma unroll
        for (int c = 0; c < 4; c++) s[i][c] = 0.f;

#pragma unroll 4
      for (int d4 = 0; d4 < DD; d4 += 4) {
        float4 qv[4], kv[4];
#pragma unroll
        for (int i = 0; i < 4; i++)
          qv[i] = *(const float4*)&Qs[(ty * 4 + i) * DD + d4];
#pragma unroll
        for (int c = 0; c < 4; c++)
          kv[c] = *(const float4*)&Ks[(tx + 16 * c) * SK + d4];
#pragma unroll
        for (int i = 0; i < 4; i++)
#pragma unroll
          for (int c = 0; c < 4; c++)
            s[i][c] += qv[i].x * kv[c].x + qv[i].y * kv[c].y +
                       qv[i].z * kv[c].z + qv[i].w * kv[c].w;
      }

      if (kt == qblk) {
#pragma unroll
        for (int i = 0; i < 4; i++) {
          const int qg = qblk * BQ + ty * 4 + i;
#pragma unroll
          for (int c = 0; c < 4; c++)
            if (kt * BK + tx + 16 * c > qg) s[i][c] = -1e30f;
        }
      }

      // ---- register softmax ----
      float vmax = s[0][0];
#pragma unroll
      for (int i = 0; i < 4; i++)
#pragma unroll
        for (int c = 0; c < 4; c++) vmax = fmaxf(vmax, s[i][c]);
#pragma unroll
      for (int off = 1; off < 16; off <<= 1)
        vmax = fmaxf(vmax, __shfl_xor_sync(0xffffffffu, vmax, off));
      const float mn = fmaxf(m, vmax);
      const float al = __expf(m - mn);
      m = mn;

#pragma unroll
      for (int i = 0; i < 4; i++) {
        float p0 = __expf(s[i][0] - mn);
        float p1 = __expf(s[i][1] - mn);
        float p2 = __expf(s[i][2] - mn);
        float p3 = __expf(s[i][3] - mn);
        s[i][0] = p0; s[i][1] = p1; s[i][2] = p2; s[i][3] = p3;
        float ps = (p0 + p1) + (p2 + p3);
#pragma unroll
        for (int off = 1; off < 16; off <<= 1)
          ps += __shfl_xor_sync(0xffffffffu, ps, off);
        lv[i] = lv[i] * al + ps;
      }

#pragma unroll
      for (int c = 0; c < 4; c++)
#pragma unroll
        for (int i = 0; i < 4; i++)
          Ps[(tx + 16 * c) * PS + ty * 4 + i] = s[i][c];
      __syncthreads();  // Ps ready; all K reads done

      if (kt + 1 < nkt) {
        const size_t krow = (size_t)(kt + 1) * BK;
#pragma unroll
        for (int it = 0; it < 8; it++)
          pv[it] = *(const float4*)&vp[(krow + lr + 8 * it) * DD + lc4];
      }

      // ---- rescale O, then O += P V ----
#pragma unroll
      for (int i = 0; i < 4; i++)
#pragma unroll
        for (int j = 0; j < 8; j++) o[i][j] *= al;

#pragma unroll 4
      for (int j = 0; j < BK; j++) {
        float p0 = Ps[j * PS + ty * 4 + 0];
        float p1 = Ps[j * PS + ty * 4 + 1];
        float p2 = Ps[j * PS + ty * 4 + 2];
        float p3 = Ps[j * PS + ty * 4 + 3];
        float4 v0 = *(const float4*)&Vs[j * DD + tx * 8];
        float4 v1 = *(const float4*)&Vs[j * DD + tx * 8 + 4];
        o[0][0] += p0 * v0.x; o[0][1] += p0 * v0.y;
        o[0][2] += p0 * v0.z; o[0][3] += p0 * v0.w;
        o[0][4] += p0 * v1.x; o[0][5] += p0 * v1.y;
        o[0][6] += p0 * v1.z; o[0][7] += p0 * v1.w;
        o[1][0] += p1 * v0.x; o[1][1] += p1 * v0.y;
        o[1][2] += p1 * v0.z; o[1][3] += p1 * v0.w;
        o[1][4] += p1 * v1.x; o[1][5] += p1 * v1.y;
        o[1][6] += p1 * v1.z; o[1][7] += p1 * v1.w;
        o[2][0] += p2 * v0.x; o[2][1] += p2 * v0.y;
        o[2][2] += p2 * v0.z; o[2][3] += p2 * v0.w;
        o[2][4] += p2 * v1.x; o[2][5] += p2 * v1.y;
        o[2][6] += p2 * v1.z; o[2][7] += p2 * v1.w;
        o[3][0] += p3 * v0.x; o[3][1] += p3 * v0.y;
        o[3][2] += p3 * v0.z; o[3][3] += p3 * v0.w;
        o[3][4] += p3 * v1.x; o[3][5] += p3 * v1.y;
        o[3][6] += p3 * v1.z; o[3][7] += p3 * v1.w;
      }
    }

    // ---- epilogue ----
#pragma unroll
    for (int i = 0; i < 4; i++) {
      const float inv = 1.f / lv[i];
      const size_t row = (size_t)b * TT + (size_t)qblk * BQ + ty * 4 + i;
      float4 a = make_float4(o[i][0] * inv, o[i][1] * inv, o[i][2] * inv,
                             o[i][3] * inv);
      float4 c = make_float4(o[i][4] * inv, o[i][5] * inv, o[i][6] * inv,
                             o[i][7] * inv);
      *(float4*)&out[row * DD + tx * 8] = a;
      *(float4*)&out[row * DD + tx * 8 + 4] = c;
    }
  }
}

// ---------------------------------------------------------------------------
extern "C" void kernel_launch(void* const* d_in, const int* in_sizes, int n_in,
                              void* d_out, int out_size) {
  const float* X = (const float*)d_in[0];
  const float* Wq = (const float*)d_in[1];
  const float* Wk = (const float*)d_in[2];
  const float* Wv = (const float*)d_in[3];
  float* out = (float*)d_out;

  qkv_gemm_kernel<<<dim3(128, 3), 256>>>(X, Wq, Wk, Wv);

  cudaFuncSetAttribute((const void*)attn_kernel,
                       cudaFuncAttributeMaxDynamicSharedMemorySize, ATT_SMEM);
  attn_kernel<<<dim3(16, BATCHN), 256, ATT_SMEM>>>(out);
}

// round 10
// speedup vs baseline: 2.5974x; 1.6641x over previous
#include <cuda_runtime.h>
#include <cuda_fp16.h>
#include <cstdint>

#define BATCHN 8
#define TT 2048
#define EE 1024
#define DD 128
#define MTOT (BATCHN*TT)

// Scratch for Q,K,V projections (8 MB each) — __device__ globals per allocation rules.
__device__ float g_q[MTOT*DD];
__device__ float g_k[MTOT*DD];
__device__ float g_v[MTOT*DD];

__device__ __forceinline__ uint32_t smem_u32(const void* p) {
  uint32_t a;
  asm("{ .reg .u64 t; cvta.to.shared.u64 t, %1; cvt.u32.u64 %0, t; }"
      : "=r"(a) : "l"(p));
  return a;
}
__device__ __forceinline__ void ldsm_x4(uint32_t* r, uint32_t addr) {
  asm volatile(
      "ldmatrix.sync.aligned.m8n8.x4.shared.b16 {%0,%1,%2,%3}, [%4];"
      : "=r"(r[0]), "=r"(r[1]), "=r"(r[2]), "=r"(r[3]) : "r"(addr));
}
__device__ __forceinline__ void mma_f16(float* c, const uint32_t* a,
                                        const uint32_t* b) {
  asm volatile(
      "mma.sync.aligned.m16n8k16.row.col.f32.f16.f16.f32 "
      "{%0,%1,%2,%3}, {%4,%5,%6,%7}, {%8,%9}, {%0,%1,%2,%3};"
      : "+f"(c[0]), "+f"(c[1]), "+f"(c[2]), "+f"(c[3])
      : "r"(a[0]), "r"(a[1]), "r"(a[2]), "r"(a[3]), "r"(b[0]), "r"(b[1]));
}

// ---------------------------------------------------------------------------
// QKV projection via fp16 HMMA (mma.sync m16n8k16) with ldmatrix feed.
// C[16384,128] = X[16384,1024] @ W[1024,128].  CTA tile 128x128, K chunk 32.
// 8 warps: warp (wm=warp>>1, wn=warp&1) computes 32(m) x 64(n).
// Smem tiles fp16, half-stride 40 (80B rows): LDSM rows hit distinct 16B
// granules (5r mod 8 bijective) -> conflict-free.  Double-buffered chunks,
// one barrier per chunk, LDG prefetch overlapped with MMA compute.
// grid = (128, 3): y selects Wq/Wk/Wv.
// ---------------------------------------------------------------------------
#define KC 32
#define HSTR 40                      // halfs per smem row
#define TILE_H (128 * HSTR)          // halfs per tile buffer

__global__ __launch_bounds__(256) void qkv_hmma_kernel(
    const float* __restrict__ X, const float* __restrict__ Wq,
    const float* __restrict__ Wk, const float* __restrict__ Wv) {
  __shared__ __half Xs[2][TILE_H];   // [m][k] halfs
  __shared__ __half Ws[2][TILE_H];   // [n][k] halfs (W transposed)

  const int which = blockIdx.y;
  const float* __restrict__ W = (which == 0) ? Wq : (which == 1) ? Wk : Wv;
  float* __restrict__ outp = (which == 0) ? g_q : (which == 1) ? g_k : g_v;

  const int m0 = blockIdx.x * 128;
  const int tid = threadIdx.x;
  const int warp = tid >> 5;
  const int lane = tid & 31;
  const int wm = (warp >> 1) * 32;   // warp m base: 0,32,64,96
  const int wn = (warp & 1) * 64;    // warp n base: 0,64

  // loader indices (both X and W stage 128 rows x 32 halfs per chunk)
  const int ldrow = tid >> 1;        // 0..127
  const int ldk = (tid & 1) * 16;    // 0 or 16

  // LDSM per-lane address components
  const int a_row = (lane & 7) + 8 * ((lane >> 3) & 1);  // 0..15
  const int a_col = (lane >> 4) * 8;                     // 0 or 8
  const int b_row = (lane & 7) + 8 * (lane >> 4);        // 0..15
  const int b_col = ((lane >> 3) & 1) * 8;               // 0 or 8

  const uint32_t xs_base = smem_u32(&Xs[0][0]);
  const uint32_t ws_base = smem_u32(&Ws[0][0]);

  float acc[2][8][4];
#pragma unroll
  for (int mt = 0; mt < 2; mt++)
#pragma unroll
    for (int nt = 0; nt < 8; nt++)
#pragma unroll
      for (int i = 0; i < 4; i++) acc[mt][nt][i] = 0.f;

  // ---- stage chunk 0 ----
  {
    float4 xv[4];
    float wv[16];
#pragma unroll
    for (int j = 0; j < 4; j++)
      xv[j] = *(const float4*)&X[(size_t)(m0 + ldrow) * EE + ldk + 4 * j];
#pragma unroll
    for (int j = 0; j < 16; j++)
      wv[j] = W[(size_t)(ldk + j) * DD + ldrow];
    __half2 hx[8], hw[8];
#pragma unroll
    for (int j = 0; j < 4; j++) {
      hx[2 * j] = __floats2half2_rn(xv[j].x, xv[j].y);
      hx[2 * j + 1] = __floats2half2_rn(xv[j].z, xv[j].w);
    }
#pragma unroll
    for (int j = 0; j < 8; j++) hw[j] = __floats2half2_rn(wv[2 * j], wv[2 * j + 1]);
    *(uint4*)&Xs[0][ldrow * HSTR + ldk] = *(uint4*)&hx[0];
    *(uint4*)&Xs[0][ldrow * HSTR + ldk + 8] = *(uint4*)&hx[4];
    *(uint4*)&Ws[0][ldrow * HSTR + ldk] = *(uint4*)&hw[0];
    *(uint4*)&Ws[0][ldrow * HSTR + ldk + 8] = *(uint4*)&hw[4];
  }
  __syncthreads();

  for (int c = 0; c < EE / KC; c++) {
    const int cur = c & 1;
    // prefetch chunk c+1 into registers (overlaps MMA below)
    float4 xv[4];
    float wv[16];
    const bool more = (c + 1 < EE / KC);
    if (more) {
      const int kc = (c + 1) * KC;
#pragma unroll
      for (int j = 0; j < 4; j++)
        xv[j] = *(const float4*)&X[(size_t)(m0 + ldrow) * EE + kc + ldk + 4 * j];
#pragma unroll
      for (int j = 0; j < 16; j++)
        wv[j] = W[(size_t)(kc + ldk + j) * DD + ldrow];
    }

    // ---- compute chunk c: 2 k16 steps ----
    const uint32_t xb = xs_base + (uint32_t)(cur * TILE_H * 2);
    const uint32_t wb = ws_base + (uint32_t)(cur * TILE_H * 2);
#pragma unroll
    for (int s = 0; s < 2; s++) {
      uint32_t a[2][4];
#pragma unroll
      for (int mt = 0; mt < 2; mt++) {
        const int row = wm + mt * 16 + a_row;
        ldsm_x4(a[mt], xb + (uint32_t)((row * HSTR + a_col + s * 16) * 2));
      }
      uint32_t bf[8][2];
#pragma unroll
      for (int g = 0; g < 4; g++) {
        uint32_t r[4];
        const int row = wn + g * 16 + b_row;
        ldsm_x4(r, wb + (uint32_t)((row * HSTR + b_col + s * 16) * 2));
        bf[2 * g][0] = r[0]; bf[2 * g][1] = r[1];
        bf[2 * g + 1][0] = r[2]; bf[2 * g + 1][1] = r[3];
      }
#pragma unroll
      for (int mt = 0; mt < 2; mt++)
#pragma unroll
        for (int nt = 0; nt < 8; nt++) mma_f16(acc[mt][nt], a[mt], bf[nt]);
    }

    // ---- stage chunk c+1 into other buffer ----
    if (more) {
      const int nxt = cur ^ 1;
      __half2 hx[8], hw[8];
#pragma unroll
      for (int j = 0; j < 4; j++) {
        hx[2 * j] = __floats2half2_rn(xv[j].x, xv[j].y);
        hx[2 * j + 1] = __floats2half2_rn(xv[j].z, xv[j].w);
      }
#pragma unroll
      for (int j = 0; j < 8; j++)
        hw[j] = __floats2half2_rn(wv[2 * j], wv[2 * j + 1]);
      *(uint4*)&Xs[nxt][ldrow * HSTR + ldk] = *(uint4*)&hx[0];
      *(uint4*)&Xs[nxt][ldrow * HSTR + ldk + 8] = *(uint4*)&hx[4];
      *(uint4*)&Ws[nxt][ldrow * HSTR + ldk] = *(uint4*)&hw[0];
      *(uint4*)&Ws[nxt][ldrow * HSTR + ldk + 8] = *(uint4*)&hw[4];
    }
    __syncthreads();
  }

  // ---- writeback (fragment layout: c0,c1 -> (t/4, 2(t%4)); c2,c3 -> +8) ----
  const int fr = lane >> 2;
  const int fc = (lane & 3) * 2;
#pragma unroll
  for (int mt = 0; mt < 2; mt++) {
    const size_t row0 = (size_t)(m0 + wm + mt * 16 + fr);
#pragma unroll
    for (int nt = 0; nt < 8; nt++) {
      const int col = wn + nt * 8 + fc;
      *(float2*)&outp[row0 * DD + col] =
          make_float2(acc[mt][nt][0], acc[mt][nt][1]);
      *(float2*)&outp[(row0 + 8) * DD + col] =
          make_float2(acc[mt][nt][2], acc[mt][nt][3]);
    }
  }
}

// ---------------------------------------------------------------------------
// Causal flash attention v6 (unchanged from R9 — 332us, 86% of SIMT floor).
// ---------------------------------------------------------------------------
#define BQ 64
#define BK 64
#define SKATT 132
#define PSATT 65
#define OFF_QS 0
#define OFF_PS (BQ * DD)
#define OFF_KS (OFF_PS + BK * PSATT)
#define OFF_VS (OFF_KS + BK * SKATT)
#define ATT_SMEM ((OFF_VS + BK * DD) * 4)

__global__ __launch_bounds__(256) void attn_kernel(float* __restrict__ out) {
  extern __shared__ float sm_[];
  float* Qs = sm_ + OFF_QS;
  float* Ps = sm_ + OFF_PS;
  float* Ks = sm_ + OFF_KS;
  float* Vs = sm_ + OFF_VS;

  const int b = blockIdx.y;
  const int tid = threadIdx.x;
  const int ty = tid >> 4;
  const int tx = tid & 15;
  const float scale = 0.08838834764831845f;

  const float* __restrict__ qp = g_q + (size_t)b * TT * DD;
  const float* __restrict__ kp = g_k + (size_t)b * TT * DD;
  const float* __restrict__ vp = g_v + (size_t)b * TT * DD;

  const int lr = tid >> 5;
  const int lc4 = (tid & 31) * 4;

  for (int pass = 0; pass < 2; pass++) {
    const int qblk = pass ? (31 - (int)blockIdx.x) : (int)blockIdx.x;
    __syncthreads();

    {
      const size_t q0 = (size_t)qblk * BQ;
#pragma unroll
      for (int it = 0; it < 8; it++) {
        const int r = lr + 8 * it;
        float4 v = *(const float4*)&qp[(q0 + r) * DD + lc4];
        v.x *= scale; v.y *= scale; v.z *= scale; v.w *= scale;
        *(float4*)&Qs[r * DD + lc4] = v;
      }
    }

    const int nkt = qblk + 1;

    float m = -1e30f;
    float lv[4] = {0.f, 0.f, 0.f, 0.f};
    float o[4][8];
#pragma unroll
    for (int i = 0; i < 4; i++)
#pragma unroll
      for (int j = 0; j < 8; j++) o[i][j] = 0.f;

    float4 pk[8], pv[8];
#pragma unroll
    for (int it = 0; it < 8; it++) {
      const int r = lr + 8 * it;
      pk[it] = *(const float4*)&kp[(size_t)r * DD + lc4];
      pv[it] = *(const float4*)&vp[(size_t)r * DD + lc4];
    }

    for (int kt = 0; kt < nkt; kt++) {
      __syncthreads();
#pragma unroll
      for (int it = 0; it < 8; it++) {
        const int r = lr + 8 * it;
        *(float4*)&Ks[r * SKATT + lc4] = pk[it];
        *(float4*)&Vs[r * DD + lc4] = pv[it];
      }
      __syncthreads();

      if (kt + 1 < nkt) {
        const size_t krow = (size_t)(kt + 1) * BK;
#pragma unroll
        for (int it = 0; it < 8; it++)
          pk[it] = *(const float4*)&kp[(krow + lr + 8 * it) * DD + lc4];
      }

      float s[4][4];
#pragma unroll
      for (int i = 0; i < 4; i++)
#pragma unroll
        for (int c = 0; c < 4; c++) s[i][c] = 0.f;

#pragma unroll 4
      for (int d4 = 0; d4 < DD; d4 += 4) {
        float4 qv[4], kv[4];
#pragma unroll
        for (int i = 0; i < 4; i++)
          qv[i] = *(const float4*)&Qs[(ty * 4 + i) * DD + d4];
#pragma unroll
        for (int c = 0; c < 4; c++)
          kv[c] = *(const float4*)&Ks[(tx + 16 * c) * SKATT + d4];
#pragma unroll
        for (int i = 0; i < 4; i++)
#pragma unroll
          for (int c = 0; c < 4; c++)
            s[i][c] += qv[i].x * kv[c].x + qv[i].y * kv[c].y +
                       qv[i].z * kv[c].z + qv[i].w * kv[c].w;
      }

      if (kt == qblk) {
#pragma unroll
        for (int i = 0; i < 4; i++) {
          const int qg = qblk * BQ + ty * 4 + i;
#pragma unroll
          for (int c = 0; c < 4; c++)
            if (kt * BK + tx + 16 * c > qg) s[i][c] = -1e30f;
        }
      }

      float vmax = s[0][0];
#pragma unroll
      for (int i = 0; i < 4; i++)
#pragma unroll
        for (int c = 0; c < 4; c++) vmax = fmaxf(vmax, s[i][c]);
#pragma unroll
      for (int off = 1; off < 16; off <<= 1)
        vmax = fmaxf(vmax, __shfl_xor_sync(0xffffffffu, vmax, off));
      const float mn = fmaxf(m, vmax);
      const float al = __expf(m - mn);
      m = mn;

#pragma unroll
      for (int i = 0; i < 4; i++) {
        float p0 = __expf(s[i][0] - mn);
        float p1 = __expf(s[i][1] - mn);
        float p2 = __expf(s[i][2] - mn);
        float p3 = __expf(s[i][3] - mn);
        s[i][0] = p0; s[i][1] = p1; s[i][2] = p2; s[i][3] = p3;
        float ps = (p0 + p1) + (p2 + p3);
#pragma unroll
        for (int off = 1; off < 16; off <<= 1)
          ps += __shfl_xor_sync(0xffffffffu, ps, off);
        lv[i] = lv[i] * al + ps;
      }

#pragma unroll
      for (int c = 0; c < 4; c++)
#pragma unroll
        for (int i = 0; i < 4; i++)
          Ps[(tx + 16 * c) * PSATT + ty * 4 + i] = s[i][c];
      __syncthreads();

      if (kt + 1 < nkt) {
        const size_t krow = (size_t)(kt + 1) * BK;
#pragma unroll
        for (int it = 0; it < 8; it++)
          pv[it] = *(const float4*)&vp[(krow + lr + 8 * it) * DD + lc4];
      }

#pragma unroll
      for (int i = 0; i < 4; i++)
#pragma unroll
        for (int j = 0; j < 8; j++) o[i][j] *= al;

#pragma unroll 4
      for (int j = 0; j < BK; j++) {
        float p0 = Ps[j * PSATT + ty * 4 + 0];
        float p1 = Ps[j * PSATT + ty * 4 + 1];
        float p2 = Ps[j * PSATT + ty * 4 + 2];
        float p3 = Ps[j * PSATT + ty * 4 + 3];
        float4 v0 = *(const float4*)&Vs[j * DD + tx * 8];
        float4 v1 = *(const float4*)&Vs[j * DD + tx * 8 + 4];
        o[0][0] += p0 * v0.x; o[0][1] += p0 * v0.y;
        o[0][2] += p0 * v0.z; o[0][3] += p0 * v0.w;
        o[0][4] += p0 * v1.x; o[0][5] += p0 * v1.y;
        o[0][6] += p0 * v1.z; o[0][7] += p0 * v1.w;
        o[1][0] += p1 * v0.x; o[1][1] += p1 * v0.y;
        o[1][2] += p1 * v0.z; o[1][3] += p1 * v0.w;
        o[1][4] += p1 * v1.x; o[1][5] += p1 * v1.y;
        o[1][6] += p1 * v1.z; o[1][7] += p1 * v1.w;
        o[2][0] += p2 * v0.x; o[2][1] += p2 * v0.y;
        o[2][2] += p2 * v0.z; o[2][3] += p2 * v0.w;
        o[2][4] += p2 * v1.x; o[2][5] += p2 * v1.y;
        o[2][6] += p2 * v1.z; o[2][7] += p2 * v1.w;
        o[3][0] += p3 * v0.x; o[3][1] += p3 * v0.y;
        o[3][2] += p3 * v0.z; o[3][3] += p3 * v0.w;
        o[3][4] += p3 * v1.x; o[3][5] += p3 * v1.y;
        o[3][6] += p3 * v1.z; o[3][7] += p3 * v1.w;
      }
    }

#pragma unroll
    for (int i = 0; i < 4; i++) {
      const float inv = 1.f / lv[i];
      const size_t row = (size_t)b * TT + (size_t)qblk * BQ + ty * 4 + i;
      float4 a = make_float4(o[i][0] * inv, o[i][1] * inv, o[i][2] * inv,
                             o[i][3] * inv);
      float4 c = make_float4(o[i][4] * inv, o[i][5] * inv, o[i][6] * inv,
                             o[i][7] * inv);
      *(float4*)&out[row * DD + tx * 8] = a;
      *(float4*)&out[row * DD + tx * 8 + 4] = c;
    }
  }
}

// ---------------------------------------------------------------------------
extern "C" void kernel_launch(void* const* d_in, const int* in_sizes, int n_in,
                              void* d_out, int out_size) {
  const float* X = (const float*)d_in[0];
  const float* Wq = (const float*)d_in[1];
  const float* Wk = (const float*)d_in[2];
  const float* Wv = (const float*)d_in[3];
  float* out = (float*)d_out;

  qkv_hmma_kernel<<<dim3(128, 3), 256>>>(X, Wq, Wk, Wv);

  cudaFuncSetAttribute((const void*)attn_kernel,
                       cudaFuncAttributeMaxDynamicSharedMemorySize, ATT_SMEM);
  attn_kernel<<<dim3(16, BATCHN), 256, ATT_SMEM>>>(out);
}

// round 11
// speedup vs baseline: 8.2990x; 3.1951x over previous
#include <cuda_runtime.h>
#include <cuda_fp16.h>
#include <cstdint>

#define BATCHN 8
#define TT 2048
#define EE 1024
#define DD 128
#define MTOT (BATCHN*TT)

// Q,K,V scratch in fp16 (4 MB each) — __device__ globals per allocation rules.
__device__ __align__(16) __half g_q[MTOT*DD];
__device__ __align__(16) __half g_k[MTOT*DD];
__device__ __align__(16) __half g_v[MTOT*DD];

__device__ __forceinline__ uint32_t smem_u32(const void* p) {
  uint32_t a;
  asm("{ .reg .u64 t; cvta.to.shared.u64 t, %1; cvt.u32.u64 %0, t; }"
      : "=r"(a) : "l"(p));
  return a;
}
__device__ __forceinline__ void ldsm_x4(uint32_t* r, uint32_t addr) {
  asm volatile(
      "ldmatrix.sync.aligned.m8n8.x4.shared.b16 {%0,%1,%2,%3}, [%4];"
      : "=r"(r[0]), "=r"(r[1]), "=r"(r[2]), "=r"(r[3]) : "r"(addr));
}
__device__ __forceinline__ void ldsm_x4_t(uint32_t* r, uint32_t addr) {
  asm volatile(
      "ldmatrix.sync.aligned.m8n8.x4.trans.shared.b16 {%0,%1,%2,%3}, [%4];"
      : "=r"(r[0]), "=r"(r[1]), "=r"(r[2]), "=r"(r[3]) : "r"(addr));
}
__device__ __forceinline__ void mma_f16(float* c, const uint32_t* a,
                                        const uint32_t* b) {
  asm volatile(
      "mma.sync.aligned.m16n8k16.row.col.f32.f16.f16.f32 "
      "{%0,%1,%2,%3}, {%4,%5,%6,%7}, {%8,%9}, {%0,%1,%2,%3};"
      : "+f"(c[0]), "+f"(c[1]), "+f"(c[2]), "+f"(c[3])
      : "r"(a[0]), "r"(a[1]), "r"(a[2]), "r"(a[3]), "r"(b[0]), "r"(b[1]));
}

// ---------------------------------------------------------------------------
// QKV projection via fp16 HMMA (R10 structure; outputs fp16, Q pre-scaled).
// ---------------------------------------------------------------------------
#define KC 32
#define HSTR 40
#define TILE_H (128 * HSTR)

__global__ __launch_bounds__(256) void qkv_hmma_kernel(
    const float* __restrict__ X, const float* __restrict__ Wq,
    const float* __restrict__ Wk, const float* __restrict__ Wv) {
  __shared__ __half Xs[2][TILE_H];
  __shared__ __half Ws[2][TILE_H];

  const int which = blockIdx.y;
  const float* __restrict__ W = (which == 0) ? Wq : (which == 1) ? Wk : Wv;
  __half* __restrict__ outp = (which == 0) ? g_q : (which == 1) ? g_k : g_v;
  const float osc = (which == 0) ? 0.08838834764831845f : 1.0f;

  const int m0 = blockIdx.x * 128;
  const int tid = threadIdx.x;
  const int warp = tid >> 5;
  const int lane = tid & 31;
  const int wm = (warp >> 1) * 32;
  const int wn = (warp & 1) * 64;

  const int ldrow = tid >> 1;
  const int ldk = (tid & 1) * 16;

  const int a_row = (lane & 7) + 8 * ((lane >> 3) & 1);
  const int a_col = (lane >> 4) * 8;
  const int b_row = (lane & 7) + 8 * (lane >> 4);
  const int b_col = ((lane >> 3) & 1) * 8;

  const uint32_t xs_base = smem_u32(&Xs[0][0]);
  const uint32_t ws_base = smem_u32(&Ws[0][0]);

  float acc[2][8][4];
#pragma unroll
  for (int mt = 0; mt < 2; mt++)
#pragma unroll
    for (int nt = 0; nt < 8; nt++)
#pragma unroll
      for (int i = 0; i < 4; i++) acc[mt][nt][i] = 0.f;

  {
    float4 xv[4];
    float wv[16];
#pragma unroll
    for (int j = 0; j < 4; j++)
      xv[j] = *(const float4*)&X[(size_t)(m0 + ldrow) * EE + ldk + 4 * j];
#pragma unroll
    for (int j = 0; j < 16; j++)
      wv[j] = W[(size_t)(ldk + j) * DD + ldrow];
    __half2 hx[8], hw[8];
#pragma unroll
    for (int j = 0; j < 4; j++) {
      hx[2 * j] = __floats2half2_rn(xv[j].x, xv[j].y);
      hx[2 * j + 1] = __floats2half2_rn(xv[j].z, xv[j].w);
    }
#pragma unroll
    for (int j = 0; j < 8; j++) hw[j] = __floats2half2_rn(wv[2 * j], wv[2 * j + 1]);
    *(uint4*)&Xs[0][ldrow * HSTR + ldk] = *(uint4*)&hx[0];
    *(uint4*)&Xs[0][ldrow * HSTR + ldk + 8] = *(uint4*)&hx[4];
    *(uint4*)&Ws[0][ldrow * HSTR + ldk] = *(uint4*)&hw[0];
    *(uint4*)&Ws[0][ldrow * HSTR + ldk + 8] = *(uint4*)&hw[4];
  }
  __syncthreads();

  for (int c = 0; c < EE / KC; c++) {
    const int cur = c & 1;
    float4 xv[4];
    float wv[16];
    const bool more = (c + 1 < EE / KC);
    if (more) {
      const int kc = (c + 1) * KC;
#pragma unroll
      for (int j = 0; j < 4; j++)
        xv[j] = *(const float4*)&X[(size_t)(m0 + ldrow) * EE + kc + ldk + 4 * j];
#pragma unroll
      for (int j = 0; j < 16; j++)
        wv[j] = W[(size_t)(kc + ldk + j) * DD + ldrow];
    }

    const uint32_t xb = xs_base + (uint32_t)(cur * TILE_H * 2);
    const uint32_t wb = ws_base + (uint32_t)(cur * TILE_H * 2);
#pragma unroll
    for (int s = 0; s < 2; s++) {
      uint32_t a[2][4];
#pragma unroll
      for (int mt = 0; mt < 2; mt++) {
        const int row = wm + mt * 16 + a_row;
        ldsm_x4(a[mt], xb + (uint32_t)((row * HSTR + a_col + s * 16) * 2));
      }
      uint32_t bf[8][2];
#pragma unroll
      for (int g = 0; g < 4; g++) {
        uint32_t r[4];
        const int row = wn + g * 16 + b_row;
        ldsm_x4(r, wb + (uint32_t)((row * HSTR + b_col + s * 16) * 2));
        bf[2 * g][0] = r[0]; bf[2 * g][1] = r[1];
        bf[2 * g + 1][0] = r[2]; bf[2 * g + 1][1] = r[3];
      }
#pragma unroll
      for (int mt = 0; mt < 2; mt++)
#pragma unroll
        for (int nt = 0; nt < 8; nt++) mma_f16(acc[mt][nt], a[mt], bf[nt]);
    }

    if (more) {
      const int nxt = cur ^ 1;
      __half2 hx[8], hw[8];
#pragma unroll
      for (int j = 0; j < 4; j++) {
        hx[2 * j] = __floats2half2_rn(xv[j].x, xv[j].y);
        hx[2 * j + 1] = __floats2half2_rn(xv[j].z, xv[j].w);
      }
#pragma unroll
      for (int j = 0; j < 8; j++)
        hw[j] = __floats2half2_rn(wv[2 * j], wv[2 * j + 1]);
      *(uint4*)&Xs[nxt][ldrow * HSTR + ldk] = *(uint4*)&hx[0];
      *(uint4*)&Xs[nxt][ldrow * HSTR + ldk + 8] = *(uint4*)&hx[4];
      *(uint4*)&Ws[nxt][ldrow * HSTR + ldk] = *(uint4*)&hw[0];
      *(uint4*)&Ws[nxt][ldrow * HSTR + ldk + 8] = *(uint4*)&hw[4];
    }
    __syncthreads();
  }

  const int fr = lane >> 2;
  const int fc = (lane & 3) * 2;
#pragma unroll
  for (int mt = 0; mt < 2; mt++) {
    const size_t row0 = (size_t)(m0 + wm + mt * 16 + fr);
#pragma unroll
    for (int nt = 0; nt < 8; nt++) {
      const int col = wn + nt * 8 + fc;
      __half2 h01 = __floats2half2_rn(acc[mt][nt][0] * osc, acc[mt][nt][1] * osc);
      __half2 h23 = __floats2half2_rn(acc[mt][nt][2] * osc, acc[mt][nt][3] * osc);
      *(__half2*)&outp[row0 * DD + col] = h01;
      *(__half2*)&outp[(row0 + 8) * DD + col] = h23;
    }
  }
}

// ---------------------------------------------------------------------------
// Causal flash attention v7: fp16 HMMA, FA2 register layout.
// ---------------------------------------------------------------------------
#define HST 136
#define QOFF 0
#define KOFF (64 * HST)
#define VOFF (128 * HST)
#define ATT_SMEM_B (192 * HST * 2)

__global__ __launch_bounds__(128) void attn_hmma_kernel(float* __restrict__ out) {
  extern __shared__ __half smh[];
  const int tid = threadIdx.x;
  const int w = tid >> 5;
  const int lane = tid & 31;
  const int b = blockIdx.y;

  const __half* __restrict__ qp = g_q + (size_t)b * TT * DD;
  const __half* __restrict__ kp = g_k + (size_t)b * TT * DD;
  const __half* __restrict__ vp = g_v + (size_t)b * TT * DD;

  const uint32_t smb = smem_u32(smh);
  const int fr = lane >> 2;
  const int fc = (lane & 3) * 2;
  const int lm = lane >> 3;
  const int r8 = lane & 7;

  const int qa_row = 16 * w + r8 + 8 * (lm & 1);
  const int qa_colb = 8 * (lm >> 1);
  const int kb_rowoff = 8 * (lm >> 1) + r8;
  const int kb_coloff = 8 * (lm & 1);
  const int vb_rowoff = 8 * (lm & 1) + r8;
  const int vb_coloff = 8 * (lm >> 1);

  const int ls_r = tid >> 4;
  const int ls_c = tid & 15;

  for (int pass = 0; pass < 2; pass++) {
    const int qblk = pass ? (31 - (int)blockIdx.x) : (int)blockIdx.x;
    const int nkt = qblk + 1;

#pragma unroll
    for (int it = 0; it < 8; it++) {
      const int r = ls_r + 8 * it;
      uint4 v = *((const uint4*)qp + (size_t)(qblk * 64 + r) * 16 + ls_c);
      *(uint4*)&smh[QOFF + r * HST + ls_c * 8] = v;
    }
    uint4 pk4[8], pv4[8];
#pragma unroll
    for (int it = 0; it < 8; it++) {
      const int r = ls_r + 8 * it;
      pk4[it] = *((const uint4*)kp + (size_t)r * 16 + ls_c);
      pv4[it] = *((const uint4*)vp + (size_t)r * 16 + ls_c);
    }
    __syncthreads();

    uint32_t qa[8][4];
#pragma unroll
    for (int ks = 0; ks < 8; ks++)
      ldsm_x4(qa[ks], smb + (uint32_t)((qa_row * HST + 16 * ks + qa_colb) * 2));

    float m0 = -1e30f, m1 = -1e30f, l0 = 0.f, l1 = 0.f;
    float ov[16][4];
#pragma unroll
    for (int nt = 0; nt < 16; nt++)
#pragma unroll
      for (int i = 0; i < 4; i++) ov[nt][i] = 0.f;

    for (int kt = 0; kt < nkt; kt++) {
      __syncthreads();
#pragma unroll
      for (int it = 0; it < 8; it++) {
        const int r = ls_r + 8 * it;
        *(uint4*)&smh[KOFF + r * HST + ls_c * 8] = pk4[it];
        *(uint4*)&smh[VOFF + r * HST + ls_c * 8] = pv4[it];
      }
      __syncthreads();

      if (kt + 1 < nkt) {
        const size_t krow = (size_t)(kt + 1) * 64;
#pragma unroll
        for (int it = 0; it < 8; it++)
          pk4[it] = *((const uint4*)kp + (krow + ls_r + 8 * it) * 16 + ls_c);
      }

      float sc_[8][4];
#pragma unroll
      for (int nt = 0; nt < 8; nt++)
#pragma unroll
        for (int i = 0; i < 4; i++) sc_[nt][i] = 0.f;

#pragma unroll
      for (int ks = 0; ks < 8; ks++) {
        uint32_t bq[4][4];
#pragma unroll
        for (int np = 0; np < 4; np++)
          ldsm_x4(bq[np], smb + (uint32_t)((KOFF + (16 * np + kb_rowoff) * HST +
                                            16 * ks + kb_coloff) * 2));
#pragma unroll
        for (int nt = 0; nt < 8; nt++)
          mma_f16(sc_[nt], qa[ks], &bq[nt >> 1][(nt & 1) * 2]);
      }

      if (kt + 1 < nkt) {
        const size_t krow = (size_t)(kt + 1) * 64;
#pragma unroll
        for (int it = 0; it < 8; it++)
          pv4[it] = *((const uint4*)vp + (krow + ls_r + 8 * it) * 16 + ls_c);
      }

      if (kt == qblk) {
        const int q0r = qblk * 64 + 16 * w + fr;
        const int q1r = q0r + 8;
#pragma unroll
        for (int nt = 0; nt < 8; nt++) {
          const int k0 = kt * 64 + nt * 8 + fc;
          if (k0 > q0r) sc_[nt][0] = -1e30f;
          if (k0 + 1 > q0r) sc_[nt][1] = -1e30f;
          if (k0 > q1r) sc_[nt][2] = -1e30f;
          if (k0 + 1 > q1r) sc_[nt][3] = -1e30f;
        }
      }

      float mx0 = sc_[0][0], mx1 = sc_[0][2];
#pragma unroll
      for (int nt = 0; nt < 8; nt++) {
        mx0 = fmaxf(mx0, fmaxf(sc_[nt][0], sc_[nt][1]));
        mx1 = fmaxf(mx1, fmaxf(sc_[nt][2], sc_[nt][3]));
      }
      mx0 = fmaxf(mx0, __shfl_xor_sync(0xffffffffu, mx0, 1));
      mx0 = fmaxf(mx0, __shfl_xor_sync(0xffffffffu, mx0, 2));
      mx1 = fmaxf(mx1, __shfl_xor_sync(0xffffffffu, mx1, 1));
      mx1 = fmaxf(mx1, __shfl_xor_sync(0xffffffffu, mx1, 2));
      const float mn0 = fmaxf(m0, mx0);
      const float mn1 = fmaxf(m1, mx1);
      const float al0 = __expf(m0 - mn0);
      const float al1 = __expf(m1 - mn1);
      m0 = mn0; m1 = mn1;

      uint32_t P2[8][2];
      float s0 = 0.f, s1 = 0.f;
#pragma unroll
      for (int nt = 0; nt < 8; nt++) {
        float p0 = __expf(sc_[nt][0] - mn0);
        float p1 = __expf(sc_[nt][1] - mn0);
        float p2 = __expf(sc_[nt][2] - mn1);
        float p3 = __expf(sc_[nt][3] - mn1);
        s0 += p0 + p1;
        s1 += p2 + p3;
        __half2 h01 = __floats2half2_rn(p0, p1);
        __half2 h23 = __floats2half2_rn(p2, p3);
        P2[nt][0] = *(uint32_t*)&h01;
        P2[nt][1] = *(uint32_t*)&h23;
      }
      s0 += __shfl_xor_sync(0xffffffffu, s0, 1);
      s0 += __shfl_xor_sync(0xffffffffu, s0, 2);
      s1 += __shfl_xor_sync(0xffffffffu, s1, 1);
      s1 += __shfl_xor_sync(0xffffffffu, s1, 2);
      l0 = l0 * al0 + s0;
      l1 = l1 * al1 + s1;

#pragma unroll
      for (int nt = 0; nt < 16; nt++) {
        ov[nt][0] *= al0; ov[nt][1] *= al0;
        ov[nt][2] *= al1; ov[nt][3] *= al1;
      }

#pragma unroll
      for (int kv = 0; kv < 4; kv++) {
        uint32_t av[4] = {P2[2 * kv][0], P2[2 * kv][1],
                          P2[2 * kv + 1][0], P2[2 * kv + 1][1]};
#pragma unroll
        for (int np = 0; np < 8; np++) {
          uint32_t bv[4];
          ldsm_x4_t(bv, smb + (uint32_t)((VOFF + (16 * kv + vb_rowoff) * HST +
                                          16 * np + vb_coloff) * 2));
          mma_f16(ov[2 * np], av, &bv[0]);
          mma_f16(ov[2 * np + 1], av, &bv[2]);
        }
      }
    }

    const float i0 = 1.f / l0;
    const float i1 = 1.f / l1;
    const size_t r0 = (size_t)b * TT + (size_t)qblk * 64 + 16 * w + fr;
#pragma unroll
    for (int nt = 0; nt < 16; nt++) {
      const int col = nt * 8 + fc;
      *(float2*)&out[r0 * DD + col] = make_float2(ov[nt][0] * i0, ov[nt][1] * i0);
      *(float2*)&out[(r0 + 8) * DD + col] =
          make_float2(ov[nt][2] * i1, ov[nt][3] * i1);
    }
  }
}

// ---------------------------------------------------------------------------
extern "C" void kernel_launch(void* const* d_in, const int* in_sizes, int n_in,
                              void* d_out, int out_size) {
  const float* X = (const float*)d_in[0];
  const float* Wq = (const float*)d_in[1];
  const float* Wk = (const float*)d_in[2];
  const float* Wv = (const float*)d_in[3];
  float* out = (float*)d_out;

  qkv_hmma_kernel<<<dim3(128, 3), 256>>>(X, Wq, Wk, Wv);

  cudaFuncSetAttribute((const void*)attn_hmma_kernel,
                       cudaFuncAttributeMaxDynamicSharedMemorySize, ATT_SMEM_B);
  attn_hmma_kernel<<<dim3(16, BATCHN), 128, ATT_SMEM_B>>>(out);
}